// round 4
// baseline (speedup 1.0000x reference)
#include <cuda_runtime.h>
#include <cuda_bf16.h>
#include <cstdint>

#define NN 100000
#define NE 1600000
#define NG 512
#define FIN 20
#define HID 128
#define OUTF 64
#define NTOT (NE + NN)

// ---------------- scratch (device globals; no allocation allowed) ----------------
__device__ __align__(16) float g_bufA[(size_t)NN * HID];   // xw (gemm output)
__device__ __align__(16) float g_bufB[(size_t)NN * HID];   // aggregated h (relu'd)
__device__ float g_dinv[NN];
__device__ int   g_deg[NN];
__device__ int   g_rowptr[NN + 1];
__device__ int   g_cursor[NN];
__device__ int   g_col[NTOT];
__device__ int   g_gcnt[NG];
__device__ int   g_gstart[NG + 1];
__device__ int   g_is64;

// dtype-agnostic index load: edge_index/batch may be int32 or int64 depending on
// the reference's JAX x64 config. g_is64 is detected at runtime from the data.
__device__ __forceinline__ int load_idx(const void* p, int is64, long long i) {
    if (is64) return (int)((const long long*)p)[i];
    return ((const int*)p)[i];
}

// ---------------- setup kernels ----------------
// If data is int64 (values < 2^31), every odd 32-bit word is 0. If int32 random
// edge endpoints, 32 consecutive odd words all being zero is impossible.
__global__ void k_detect(const int* __restrict__ ei32) {
    int z = 0;
    #pragma unroll
    for (int i = 1; i < 64; i += 2) z |= ei32[i];
    g_is64 = (z == 0) ? 1 : 0;
}

__global__ void k_zero_gcnt() {
    int t = threadIdx.x;
    if (t < NG) g_gcnt[t] = 0;
}

__global__ void k_init(const void* __restrict__ batch) {
    int i = blockIdx.x * blockDim.x + threadIdx.x;
    if (i < NN) {
        g_deg[i] = 1;                               // self loop
        int b = load_idx(batch, g_is64, i);
        atomicAdd(&g_gcnt[b], 1);
    }
}

__global__ void k_degcount(const void* __restrict__ ei) {
    int e = blockIdx.x * blockDim.x + threadIdx.x;
    if (e < NE) {
        int d = load_idx(ei, g_is64, (long long)NE + e);   // dst row
        atomicAdd(&g_deg[d], 1);
    }
}

__global__ void k_dinv() {
    int i = blockIdx.x * blockDim.x + threadIdx.x;
    if (i < NN) g_dinv[i] = rsqrtf((float)g_deg[i]);
}

// single-block exclusive scan of g_deg -> g_rowptr, g_cursor
__global__ void k_scan_deg() {
    const int n = NN;
    int t = threadIdx.x, lane = t & 31, w = t >> 5;
    int nwarps = blockDim.x >> 5;
    __shared__ int wsum[32];
    int carry = 0;
    for (int base = 0; base < n; base += blockDim.x) {
        int i = base + t;
        int v = (i < n) ? g_deg[i] : 0;
        int x = v;
        #pragma unroll
        for (int o = 1; o < 32; o <<= 1) {
            int y = __shfl_up_sync(0xffffffffu, x, o);
            if (lane >= o) x += y;
        }
        if (lane == 31) wsum[w] = x;
        __syncthreads();
        if (w == 0) {
            int s = (lane < nwarps) ? wsum[lane] : 0;
            #pragma unroll
            for (int o = 1; o < 32; o <<= 1) {
                int y = __shfl_up_sync(0xffffffffu, s, o);
                if (lane >= o) s += y;
            }
            wsum[lane] = s;
        }
        __syncthreads();
        int incl = x + (w > 0 ? wsum[w - 1] : 0);
        int total = wsum[31];
        if (i < n) {
            int ex = carry + incl - v;
            g_rowptr[i] = ex;
            g_cursor[i] = ex;
        }
        carry += total;
        __syncthreads();
    }
    if (t == 0) g_rowptr[n] = carry;
}

// single-block exclusive scan of g_gcnt -> g_gstart (n = 512 == blockDim)
__global__ void k_scan_g() {
    int t = threadIdx.x, lane = t & 31, w = t >> 5;
    int nwarps = blockDim.x >> 5;
    __shared__ int wsum[32];
    int v = g_gcnt[t];
    int x = v;
    #pragma unroll
    for (int o = 1; o < 32; o <<= 1) {
        int y = __shfl_up_sync(0xffffffffu, x, o);
        if (lane >= o) x += y;
    }
    if (lane == 31) wsum[w] = x;
    __syncthreads();
    if (w == 0) {
        int s = (lane < nwarps) ? wsum[lane] : 0;
        #pragma unroll
        for (int o = 1; o < 32; o <<= 1) {
            int y = __shfl_up_sync(0xffffffffu, s, o);
            if (lane >= o) s += y;
        }
        wsum[lane] = s;
    }
    __syncthreads();
    int incl = x + (w > 0 ? wsum[w - 1] : 0);
    g_gstart[t] = incl - v;
    if (t == 0) g_gstart[NG] = wsum[31];
}

__global__ void k_scatter(const void* __restrict__ ei) {
    int e = blockIdx.x * blockDim.x + threadIdx.x;
    if (e >= NTOT) return;
    int s, d;
    if (e < NE) {
        s = load_idx(ei, g_is64, e);
        d = load_idx(ei, g_is64, (long long)NE + e);
    } else {
        s = d = e - NE;
    }
    int pos = atomicAdd(&g_cursor[d], 1);
    g_col[pos] = s;
}

// ---------------- GEMM kernels ----------------
// x[N,20] @ W1[20,128] -> g_bufA. 64 nodes/block, 256 threads.
__global__ void k_gemm1(const float* __restrict__ x, const float* __restrict__ W1) {
    __shared__ __align__(16) float Wsh[FIN * HID];  // 10 KB
    __shared__ float xsh[64 * FIN];                 // 5 KB
    int t = threadIdx.x;
    int bn = blockIdx.x * 64;
    for (int i = t; i < FIN * HID; i += 256) Wsh[i] = W1[i];
    for (int i = t; i < 64 * FIN; i += 256) {
        int n = i / FIN, k = i % FIN;
        xsh[i] = (bn + n < NN) ? x[(size_t)(bn + n) * FIN + k] : 0.0f;
    }
    __syncthreads();
    int g = t >> 5, c4 = (t & 31) * 4;
    float4 acc[8];
    #pragma unroll
    for (int i = 0; i < 8; i++) acc[i] = make_float4(0.f, 0.f, 0.f, 0.f);
    for (int k = 0; k < FIN; k++) {
        float4 wv = *(const float4*)&Wsh[k * HID + c4];
        #pragma unroll
        for (int i = 0; i < 8; i++) {
            float xv = xsh[(g * 8 + i) * FIN + k];
            acc[i].x += wv.x * xv; acc[i].y += wv.y * xv;
            acc[i].z += wv.z * xv; acc[i].w += wv.w * xv;
        }
    }
    #pragma unroll
    for (int i = 0; i < 8; i++) {
        int n = bn + g * 8 + i;
        if (n < NN) *(float4*)&g_bufA[(size_t)n * HID + c4] = acc[i];
    }
}

// g_bufB[N,128] @ W[128,128] -> g_bufA. 64 nodes/block, 256 threads, 32-k chunks.
__global__ void k_gemm_hid(const float* __restrict__ W) {
    __shared__ __align__(16) float Wsh[32 * HID];   // 16 KB
    __shared__ __align__(16) float xsh[64 * 32];    // 8 KB
    int t = threadIdx.x;
    int bn = blockIdx.x * 64;
    int g = t >> 5, c4 = (t & 31) * 4;
    float4 acc[8];
    #pragma unroll
    for (int i = 0; i < 8; i++) acc[i] = make_float4(0.f, 0.f, 0.f, 0.f);
    for (int kc = 0; kc < 4; kc++) {
        for (int i = t * 4; i < 32 * HID; i += 1024)
            *(float4*)&Wsh[i] = *(const float4*)&W[kc * 32 * HID + i];
        for (int f = t; f < 512; f += 256) {
            int n = f >> 3, kk4 = (f & 7) * 4;
            float4 v = (bn + n < NN)
                ? *(const float4*)&g_bufB[(size_t)(bn + n) * HID + kc * 32 + kk4]
                : make_float4(0.f, 0.f, 0.f, 0.f);
            *(float4*)&xsh[n * 32 + kk4] = v;
        }
        __syncthreads();
        #pragma unroll 8
        for (int kk = 0; kk < 32; kk++) {
            float4 wv = *(const float4*)&Wsh[kk * HID + c4];
            #pragma unroll
            for (int i = 0; i < 8; i++) {
                float xv = xsh[(g * 8 + i) * 32 + kk];
                acc[i].x += wv.x * xv; acc[i].y += wv.y * xv;
                acc[i].z += wv.z * xv; acc[i].w += wv.w * xv;
            }
        }
        __syncthreads();
    }
    #pragma unroll
    for (int i = 0; i < 8; i++) {
        int n = bn + g * 8 + i;
        if (n < NN) *(float4*)&g_bufA[(size_t)n * HID + c4] = acc[i];
    }
}

// ---------------- aggregation: gather-only CSR, warp per node ----------------
// out[d] = relu( dinv[d] * sum_e xw[src_e]*dinv[src_e] + b ), xw = g_bufA -> g_bufB
__global__ void k_agg(const float* __restrict__ bias) {
    int wid = (blockIdx.x * blockDim.x + threadIdx.x) >> 5;
    int lane = threadIdx.x & 31;
    if (wid >= NN) return;
    int r = g_rowptr[wid];
    int e = g_rowptr[wid + 1];
    float4 acc = make_float4(0.f, 0.f, 0.f, 0.f);
    for (int j = r; j < e; j++) {
        int s = g_col[j];                       // broadcast
        float w = g_dinv[s];                    // broadcast
        float4 v = *(const float4*)&g_bufA[(size_t)s * HID + lane * 4];
        acc.x += v.x * w; acc.y += v.y * w;
        acc.z += v.z * w; acc.w += v.w * w;
    }
    float dn = g_dinv[wid];
    float4 b = *(const float4*)&bias[lane * 4];
    float4 o;
    o.x = fmaxf(acc.x * dn + b.x, 0.f);
    o.y = fmaxf(acc.y * dn + b.y, 0.f);
    o.z = fmaxf(acc.z * dn + b.z, 0.f);
    o.w = fmaxf(acc.w * dn + b.w, 0.f);
    *(float4*)&g_bufB[(size_t)wid * HID + lane * 4] = o;
}

// ---------------- mean-pool (sorted batch -> contiguous ranges) + output GEMM ----------------
__global__ void k_pool(const float* __restrict__ Wout, const float* __restrict__ bout,
                       float* __restrict__ out) {
    int gg = blockIdx.x;
    int t = threadIdx.x;  // 128
    int st = g_gstart[gg], en = g_gstart[gg + 1];
    float acc = 0.f;
    for (int n = st; n < en; n++) acc += g_bufB[(size_t)n * HID + t];
    __shared__ float pooled[HID];
    float cnt = (float)(en - st);
    if (cnt < 1.f) cnt = 1.f;
    pooled[t] = acc / cnt;
    __syncthreads();
    if (t < OUTF) {
        float o = bout[t];
        #pragma unroll 8
        for (int k = 0; k < HID; k++) o += pooled[k] * Wout[k * OUTF + t];
        out[(size_t)gg * OUTF + t] = o;
    }
}

// ---------------- launcher ----------------
extern "C" void kernel_launch(void* const* d_in, const int* in_sizes, int n_in,
                              void* d_out, int out_size) {
    const float* x     = (const float*)d_in[0];
    const void*  ei    = d_in[1];
    const void*  batch = d_in[2];
    const float* W1 = (const float*)d_in[3];  const float* b1 = (const float*)d_in[4];
    const float* W2 = (const float*)d_in[5];  const float* b2 = (const float*)d_in[6];
    const float* W3 = (const float*)d_in[7];  const float* b3 = (const float*)d_in[8];
    const float* Wout = (const float*)d_in[9]; const float* bout = (const float*)d_in[10];
    float* out = (float*)d_out;

    // --- graph structure (once per launch, amortized over 3 layers) ---
    k_detect<<<1, 1>>>((const int*)ei);
    k_zero_gcnt<<<1, 512>>>();
    k_init<<<(NN + 255) / 256, 256>>>(batch);
    k_degcount<<<(NE + 255) / 256, 256>>>(ei);
    k_dinv<<<(NN + 255) / 256, 256>>>();
    k_scan_deg<<<1, 1024>>>();
    k_scan_g<<<1, 512>>>();
    k_scatter<<<(NTOT + 255) / 256, 256>>>(ei);

    const int gemm_blocks = (NN + 63) / 64;
    const int agg_blocks  = (NN + 7) / 8;     // 8 warps/block, warp per node

    // --- layer 1 ---
    k_gemm1<<<gemm_blocks, 256>>>(x, W1);
    k_agg<<<agg_blocks, 256>>>(b1);
    // --- layer 2 ---
    k_gemm_hid<<<gemm_blocks, 256>>>(W2);
    k_agg<<<agg_blocks, 256>>>(b2);
    // --- layer 3 ---
    k_gemm_hid<<<gemm_blocks, 256>>>(W3);
    k_agg<<<agg_blocks, 256>>>(b3);

    // --- pool + head ---
    k_pool<<<NG, HID>>>(Wout, bout, out);
}

// round 5
// speedup vs baseline: 2.0778x; 2.0778x over previous
#include <cuda_runtime.h>
#include <cuda_fp16.h>
#include <cstdint>

#define NN 100000
#define NE 1600000
#define NG 512
#define FIN 20
#define HID 128
#define OUTF 64
#define NTOT (NE + NN)
#define NSCAN_BLK ((NN + 1023) / 1024)   // 98

// ---------------- scratch (device globals; no allocation allowed) ----------------
__device__ __align__(16) float  g_ax[(size_t)NN * FIN];    // aggregated x (layer-1 pre-GEMM)
__device__ __align__(16) __half g_h[(size_t)NN * HID];     // node features (post relu), fp16
__device__ __align__(16) __half g_xw[(size_t)NN * HID];    // gemm output * dinv[row], fp16
__device__ __align__(16) __half g_Wt[2][HID * HID];        // W2^T, W3^T in fp16 (n-major)
__device__ float g_dinv[NN];
__device__ int   g_deg[NN];
__device__ int   g_rowptr[NN + 1];
__device__ int   g_cursor[NN];
__device__ int   g_col[NTOT];
__device__ int   g_part[NSCAN_BLK + 32];
__device__ int   g_gcnt[NG];
__device__ int   g_gstart[NG + 1];
__device__ int   g_is64;

// dtype-agnostic index load (edge_index/batch may be int32 or int64)
__device__ __forceinline__ int load_idx(const void* p, int is64, long long i) {
    if (is64) return (int)((const long long*)p)[i];
    return ((const int*)p)[i];
}

// ---------------- mma / ldmatrix wrappers ----------------
__device__ __forceinline__ void ldsm_x4(uint32_t addr, uint32_t& r0, uint32_t& r1,
                                        uint32_t& r2, uint32_t& r3) {
    asm volatile("ldmatrix.sync.aligned.m8n8.x4.shared.b16 {%0,%1,%2,%3}, [%4];"
                 : "=r"(r0), "=r"(r1), "=r"(r2), "=r"(r3) : "r"(addr));
}
__device__ __forceinline__ void ldsm_x2(uint32_t addr, uint32_t& r0, uint32_t& r1) {
    asm volatile("ldmatrix.sync.aligned.m8n8.x2.shared.b16 {%0,%1}, [%2];"
                 : "=r"(r0), "=r"(r1) : "r"(addr));
}
__device__ __forceinline__ void mma16816(float* c, uint32_t a0, uint32_t a1, uint32_t a2,
                                         uint32_t a3, uint32_t b0, uint32_t b1) {
    asm volatile(
        "mma.sync.aligned.m16n8k16.row.col.f32.f16.f16.f32 "
        "{%0,%1,%2,%3},{%4,%5,%6,%7},{%8,%9},{%0,%1,%2,%3};"
        : "+f"(c[0]), "+f"(c[1]), "+f"(c[2]), "+f"(c[3])
        : "r"(a0), "r"(a1), "r"(a2), "r"(a3), "r"(b0), "r"(b1));
}

// ---------------- setup kernels ----------------
__global__ void k_detect(const int* __restrict__ ei32) {
    int z = 0;
    #pragma unroll
    for (int i = 1; i < 64; i += 2) z |= ei32[i];
    g_is64 = (z == 0) ? 1 : 0;
}

__global__ void k_zero_gcnt() {
    int t = threadIdx.x;
    if (t < NG) g_gcnt[t] = 0;
}

__global__ void k_init(const void* __restrict__ batch) {
    int i = blockIdx.x * blockDim.x + threadIdx.x;
    if (i < NN) {
        g_deg[i] = 1;                               // self loop
        atomicAdd(&g_gcnt[load_idx(batch, g_is64, i)], 1);
    }
}

__global__ void k_degcount(const void* __restrict__ ei) {
    int e = blockIdx.x * blockDim.x + threadIdx.x;
    if (e < NE) {
        int d = load_idx(ei, g_is64, (long long)NE + e);
        atomicAdd(&g_deg[d], 1);
    }
}

__global__ void k_dinv() {
    int i = blockIdx.x * blockDim.x + threadIdx.x;
    if (i < NN) g_dinv[i] = rsqrtf((float)g_deg[i]);
}

// convert + transpose weights to fp16: g_Wt[w][n*128+k] = W[k*128+n]
__global__ void k_wconv(const float* __restrict__ W2, const float* __restrict__ W3) {
    int id = blockIdx.x * blockDim.x + threadIdx.x;  // 0..32767
    int w = id >> 14;
    int e = id & 16383;
    int n = e >> 7, k = e & 127;
    const float* W = w ? W3 : W2;
    g_Wt[w][n * HID + k] = __float2half_rn(W[k * HID + n]);
}

// ---------------- multi-block scan of g_deg -> g_rowptr/g_cursor ----------------
// pass 1: per-1024-chunk sums
__global__ void k_scan_part() {
    int b = blockIdx.x, t = threadIdx.x;
    int base = b * 1024 + t * 4;
    int s = 0;
    #pragma unroll
    for (int i = 0; i < 4; i++) {
        int idx = base + i;
        if (idx < NN) s += g_deg[idx];
    }
    #pragma unroll
    for (int o = 16; o; o >>= 1) s += __shfl_down_sync(0xffffffffu, s, o);
    __shared__ int ws[8];
    if ((t & 31) == 0) ws[t >> 5] = s;
    __syncthreads();
    if (t == 0) {
        int tot = 0;
        #pragma unroll
        for (int i = 0; i < 8; i++) tot += ws[i];
        g_part[b] = tot;
    }
}

// pass 2: exclusive scan of partials (single block, 128 threads >= NSCAN_BLK)
__global__ void k_scan_part2() {
    int t = threadIdx.x, lane = t & 31, w = t >> 5;
    __shared__ int wsum[4];
    int v = (t < NSCAN_BLK) ? g_part[t] : 0;
    int x = v;
    #pragma unroll
    for (int o = 1; o < 32; o <<= 1) {
        int y = __shfl_up_sync(0xffffffffu, x, o);
        if (lane >= o) x += y;
    }
    if (lane == 31) wsum[w] = x;
    __syncthreads();
    if (t == 0) {
        int run = 0;
        #pragma unroll
        for (int i = 0; i < 4; i++) { int tmp = wsum[i]; wsum[i] = run; run += tmp; }
    }
    __syncthreads();
    if (t < NSCAN_BLK) g_part[t] = x - v + wsum[w];
    if (t == 0) g_rowptr[NN] = NTOT;
}

// pass 3: local exclusive re-scan + offset -> rowptr/cursor
__global__ void k_scan_final() {
    int b = blockIdx.x, t = threadIdx.x, lane = t & 31, w = t >> 5;
    int base = b * 1024 + t * 4;
    int v[4];
    int tsum = 0;
    #pragma unroll
    for (int i = 0; i < 4; i++) {
        v[i] = (base + i < NN) ? g_deg[base + i] : 0;
        tsum += v[i];
    }
    int x = tsum;
    #pragma unroll
    for (int o = 1; o < 32; o <<= 1) {
        int y = __shfl_up_sync(0xffffffffu, x, o);
        if (lane >= o) x += y;
    }
    __shared__ int wsum[8];
    if (lane == 31) wsum[w] = x;
    __syncthreads();
    if (t == 0) {
        int run = 0;
        #pragma unroll
        for (int i = 0; i < 8; i++) { int tmp = wsum[i]; wsum[i] = run; run += tmp; }
    }
    __syncthreads();
    int run = x - tsum + wsum[w] + g_part[b];
    #pragma unroll
    for (int i = 0; i < 4; i++) {
        if (base + i < NN) {
            g_rowptr[base + i] = run;
            g_cursor[base + i] = run;
            run += v[i];
        }
    }
}

// single-block exclusive scan of g_gcnt -> g_gstart
__global__ void k_scan_g() {
    int t = threadIdx.x, lane = t & 31, w = t >> 5;
    int nwarps = blockDim.x >> 5;
    __shared__ int wsum[32];
    int v = g_gcnt[t];
    int x = v;
    #pragma unroll
    for (int o = 1; o < 32; o <<= 1) {
        int y = __shfl_up_sync(0xffffffffu, x, o);
        if (lane >= o) x += y;
    }
    if (lane == 31) wsum[w] = x;
    __syncthreads();
    if (w == 0) {
        int s = (lane < nwarps) ? wsum[lane] : 0;
        #pragma unroll
        for (int o = 1; o < 32; o <<= 1) {
            int y = __shfl_up_sync(0xffffffffu, s, o);
            if (lane >= o) s += y;
        }
        wsum[lane] = s;
    }
    __syncthreads();
    int incl = x + (w > 0 ? wsum[w - 1] : 0);
    g_gstart[t] = incl - v;
    if (t == 0) g_gstart[NG] = wsum[31];
}

__global__ void k_scatter(const void* __restrict__ ei) {
    int e = blockIdx.x * blockDim.x + threadIdx.x;
    if (e >= NTOT) return;
    int s, d;
    if (e < NE) {
        s = load_idx(ei, g_is64, e);
        d = load_idx(ei, g_is64, (long long)NE + e);
    } else {
        s = d = e - NE;
    }
    int pos = atomicAdd(&g_cursor[d], 1);
    g_col[pos] = s;
}

// ---------------- layer 1: aggregate raw x (20 feats), then small GEMM ----------------
// g_ax[d] = dinv[d] * sum_e dinv[s] * x[s]
__global__ void k_agg_x(const float* __restrict__ x) {
    int wid = (blockIdx.x * blockDim.x + threadIdx.x) >> 5;
    int lane = threadIdx.x & 31;
    if (wid >= NN) return;
    int r = g_rowptr[wid], e = g_rowptr[wid + 1];
    float acc = 0.f;
    for (int j = r; j < e; j++) {
        int s = g_col[j];
        float w = g_dinv[s];
        if (lane < FIN) acc += w * x[(size_t)s * FIN + lane];
    }
    if (lane < FIN) g_ax[(size_t)wid * FIN + lane] = acc * g_dinv[wid];
}

// g_ax[N,20] @ W1[20,128] + b1, relu -> g_h (fp16). 64 nodes/block, 256 threads.
__global__ void k_gemm1(const float* __restrict__ W1, const float* __restrict__ b1) {
    __shared__ __align__(16) float Wsh[FIN * HID];
    __shared__ float xsh[64 * FIN];
    int t = threadIdx.x;
    int bn = blockIdx.x * 64;
    for (int i = t; i < FIN * HID; i += 256) Wsh[i] = W1[i];
    for (int i = t; i < 64 * FIN; i += 256) {
        int n = i / FIN, k = i % FIN;
        xsh[i] = (bn + n < NN) ? g_ax[(size_t)(bn + n) * FIN + k] : 0.0f;
    }
    __syncthreads();
    int g = t >> 5, c4 = (t & 31) * 4;
    float4 acc[8];
    #pragma unroll
    for (int i = 0; i < 8; i++) acc[i] = make_float4(0.f, 0.f, 0.f, 0.f);
    for (int k = 0; k < FIN; k++) {
        float4 wv = *(const float4*)&Wsh[k * HID + c4];
        #pragma unroll
        for (int i = 0; i < 8; i++) {
            float xv = xsh[(g * 8 + i) * FIN + k];
            acc[i].x += wv.x * xv; acc[i].y += wv.y * xv;
            acc[i].z += wv.z * xv; acc[i].w += wv.w * xv;
        }
    }
    float4 bb = *(const float4*)&b1[c4];
    #pragma unroll
    for (int i = 0; i < 8; i++) {
        int n = bn + g * 8 + i;
        if (n < NN) {
            float ox = fmaxf(acc[i].x + bb.x, 0.f), oy = fmaxf(acc[i].y + bb.y, 0.f);
            float oz = fmaxf(acc[i].z + bb.z, 0.f), ow = fmaxf(acc[i].w + bb.w, 0.f);
            __half2 h0 = __floats2half2_rn(ox, oy);
            __half2 h1 = __floats2half2_rn(oz, ow);
            __half2* p = (__half2*)&g_h[(size_t)n * HID + c4];
            p[0] = h0; p[1] = h1;
        }
    }
}

// ---------------- hidden GEMM: g_h[N,128] @ W[128,128], * dinv[row] -> g_xw fp16 ----------------
// tensor cores: tile 64 rows x 128 cols, 8 warps (4 m-tiles x 2 n-halves)
__global__ __launch_bounds__(256, 2) void k_gemm_mma(int widx) {
    __shared__ __align__(16) __half Ash[64 * HID];    // 16 KB, swizzled
    __shared__ __align__(16) __half Wsh[HID * HID];   // 32 KB, swizzled
    int t = threadIdx.x;
    int bn = blockIdx.x * 64;

    // load A tile (64 rows x 128 half) with 16B-chunk xor swizzle
    for (int i = t; i < 64 * 16; i += 256) {
        int row = i >> 4, ch = i & 15;
        int gr = bn + row;
        uint4 v = make_uint4(0u, 0u, 0u, 0u);
        if (gr < NN) v = *(const uint4*)&g_h[(size_t)gr * HID + ch * 8];
        *(uint4*)((char*)Ash + row * 256 + ((ch ^ (row & 7)) << 4)) = v;
    }
    // load W^T tile (128 x 128 half)
    const __half* Wt = g_Wt[widx];
    for (int i = t; i < 128 * 16; i += 256) {
        int row = i >> 4, ch = i & 15;
        uint4 v = *(const uint4*)&Wt[(size_t)row * HID + ch * 8];
        *(uint4*)((char*)Wsh + row * 256 + ((ch ^ (row & 7)) << 4)) = v;
    }
    __syncthreads();

    int w = t >> 5, lane = t & 31;
    int mb = (w & 3) * 16;          // m within tile
    int nb = (w >> 2) * 8;          // ntile base (8 ntiles per warp)
    uint32_t AshB = (uint32_t)__cvta_generic_to_shared(Ash);
    uint32_t WshB = (uint32_t)__cvta_generic_to_shared(Wsh);

    float c[8][4];
    #pragma unroll
    for (int i = 0; i < 8; i++)
        #pragma unroll
        for (int j = 0; j < 4; j++) c[i][j] = 0.f;

    int sel = lane >> 3, r8 = lane & 7;
    #pragma unroll
    for (int ks = 0; ks < 8; ks++) {
        int arow = mb + r8 + ((sel & 1) << 3);
        int ach = ks * 2 + (sel >> 1);
        uint32_t a0, a1, a2, a3;
        ldsm_x4(AshB + arow * 256 + ((ach ^ (arow & 7)) << 4), a0, a1, a2, a3);
        int bch = ks * 2 + ((lane >> 3) & 1);
        #pragma unroll
        for (int nt = 0; nt < 8; nt++) {
            int brow = (nb + nt) * 8 + r8;
            uint32_t b0, b1;
            ldsm_x2(WshB + brow * 256 + ((bch ^ (brow & 7)) << 4), b0, b1);
            mma16816(c[nt], a0, a1, a2, a3, b0, b1);
        }
    }

    int r1 = bn + mb + (lane >> 2);
    int r2 = r1 + 8;
    float s1 = (r1 < NN) ? g_dinv[r1] : 0.f;
    float s2 = (r2 < NN) ? g_dinv[r2] : 0.f;
    #pragma unroll
    for (int nt = 0; nt < 8; nt++) {
        int col = (nb + nt) * 8 + (lane & 3) * 2;
        if (r1 < NN)
            *(__half2*)&g_xw[(size_t)r1 * HID + col] = __floats2half2_rn(c[nt][0] * s1, c[nt][1] * s1);
        if (r2 < NN)
            *(__half2*)&g_xw[(size_t)r2 * HID + col] = __floats2half2_rn(c[nt][2] * s2, c[nt][3] * s2);
    }
}

// ---------------- aggregation (hidden layers): gather fp16, fused bias+relu ----------------
// g_h[d] = relu( dinv[d] * sum_e g_xw[s] + b )   (g_xw already scaled by dinv[s])
__global__ void k_agg_h(const float* __restrict__ bias) {
    int wid = (blockIdx.x * blockDim.x + threadIdx.x) >> 5;
    int lane = threadIdx.x & 31;
    if (wid >= NN) return;
    int r = g_rowptr[wid], e = g_rowptr[wid + 1];
    float4 acc = make_float4(0.f, 0.f, 0.f, 0.f);
    for (int j = r; j < e; j++) {
        int s = g_col[j];
        uint2 v = *(const uint2*)&g_xw[(size_t)s * HID + lane * 4];
        float2 f0 = __half22float2(*(__half2*)&v.x);
        float2 f1 = __half22float2(*(__half2*)&v.y);
        acc.x += f0.x; acc.y += f0.y; acc.z += f1.x; acc.w += f1.y;
    }
    float dn = g_dinv[wid];
    float4 b = *(const float4*)&bias[lane * 4];
    float ox = fmaxf(acc.x * dn + b.x, 0.f), oy = fmaxf(acc.y * dn + b.y, 0.f);
    float oz = fmaxf(acc.z * dn + b.z, 0.f), ow = fmaxf(acc.w * dn + b.w, 0.f);
    __half2* p = (__half2*)&g_h[(size_t)wid * HID + lane * 4];
    p[0] = __floats2half2_rn(ox, oy);
    p[1] = __floats2half2_rn(oz, ow);
}

// ---------------- mean-pool + output head ----------------
__global__ void k_pool(const float* __restrict__ Wout, const float* __restrict__ bout,
                       float* __restrict__ out) {
    int gg = blockIdx.x;
    int t = threadIdx.x;  // 128
    int st = g_gstart[gg], en = g_gstart[gg + 1];
    float acc = 0.f;
    for (int n = st; n < en; n++) acc += __half2float(g_h[(size_t)n * HID + t]);
    __shared__ float pooled[HID];
    float cnt = (float)(en - st);
    if (cnt < 1.f) cnt = 1.f;
    pooled[t] = acc / cnt;
    __syncthreads();
    if (t < OUTF) {
        float o = bout[t];
        #pragma unroll 8
        for (int k = 0; k < HID; k++) o += pooled[k] * Wout[k * OUTF + t];
        out[(size_t)gg * OUTF + t] = o;
    }
}

// ---------------- launcher ----------------
extern "C" void kernel_launch(void* const* d_in, const int* in_sizes, int n_in,
                              void* d_out, int out_size) {
    const float* x     = (const float*)d_in[0];
    const void*  ei    = d_in[1];
    const void*  batch = d_in[2];
    const float* W1 = (const float*)d_in[3];  const float* b1 = (const float*)d_in[4];
    const float* W2 = (const float*)d_in[5];  const float* b2 = (const float*)d_in[6];
    const float* W3 = (const float*)d_in[7];  const float* b3 = (const float*)d_in[8];
    const float* Wout = (const float*)d_in[9]; const float* bout = (const float*)d_in[10];
    float* out = (float*)d_out;

    // --- graph structure + weight prep ---
    k_detect<<<1, 1>>>((const int*)ei);
    k_zero_gcnt<<<1, 512>>>();
    k_init<<<(NN + 255) / 256, 256>>>(batch);
    k_degcount<<<(NE + 255) / 256, 256>>>(ei);
    k_dinv<<<(NN + 255) / 256, 256>>>();
    k_wconv<<<64, 512>>>(W2, W3);
    k_scan_part<<<NSCAN_BLK, 256>>>();
    k_scan_part2<<<1, 128>>>();
    k_scan_final<<<NSCAN_BLK, 256>>>();
    k_scan_g<<<1, 512>>>();
    k_scatter<<<(NTOT + 255) / 256, 256>>>(ei);

    const int agg_blocks  = (NN + 7) / 8;       // warp per node
    const int mma_blocks  = (NN + 63) / 64;

    // --- layer 1: aggregate x first, then GEMM ---
    k_agg_x<<<agg_blocks, 256>>>(x);
    k_gemm1<<<(NN + 63) / 64, 256>>>(W1, b1);
    // --- layer 2 ---
    k_gemm_mma<<<mma_blocks, 256>>>(0);
    k_agg_h<<<agg_blocks, 256>>>(b2);
    // --- layer 3 ---
    k_gemm_mma<<<mma_blocks, 256>>>(1);
    k_agg_h<<<agg_blocks, 256>>>(b3);

    // --- pool + head ---
    k_pool<<<NG, HID>>>(Wout, bout, out);
}